// round 1
// baseline (speedup 1.0000x reference)
#include <cuda_runtime.h>
#include <cuda_bf16.h>

// Problem constants (hardcoded per reference)
#define E_TOT   10000
#define CI_DIM  16
#define CO_DIM  16
#define FREQ    44
#define IN_DIM  16
#define OUT_DIM 16
#define EDGE_F  16
#define MID     32
#define LN_EPS  1e-5f

#define EB 8                 // edges per block in main kernel
#define NBLK (E_TOT / EB)    // 1250

// scratch for MLP output h[E,32]
__device__ float g_h[E_TOT * MID];

// ---------------------------------------------------------------------------
// Kernel 1: RadialProfile MLP front (Linear->LN->ReLU->Linear->LN->ReLU)
// warp per edge, lane = hidden unit m (0..31)
// ---------------------------------------------------------------------------
__device__ __forceinline__ float ln_relu_32(float y, float gamma, float beta) {
    // LayerNorm across the 32 lanes of the warp, then ReLU
    float s = y, q = y * y;
    #pragma unroll
    for (int d = 16; d > 0; d >>= 1) {
        s += __shfl_xor_sync(0xffffffffu, s, d);
        q += __shfl_xor_sync(0xffffffffu, q, d);
    }
    float mean = s * (1.0f / 32.0f);
    float var  = q * (1.0f / 32.0f) - mean * mean;
    float r = rsqrtf(var + LN_EPS);
    float v = (y - mean) * r * gamma + beta;
    return fmaxf(v, 0.0f);
}

__global__ void __launch_bounds__(256) mlp_kernel(
    const float* __restrict__ inv,   // [E,16]
    const float* __restrict__ w1,    // [32,16]
    const float* __restrict__ b1,
    const float* __restrict__ g1,
    const float* __restrict__ be1,
    const float* __restrict__ w2,    // [32,32]
    const float* __restrict__ b2,
    const float* __restrict__ g2,
    const float* __restrict__ be2)
{
    __shared__ float w1_s[32 * 16];
    __shared__ float w2_s[32 * 32];
    __shared__ float p_s[6 * 32];

    int tid = threadIdx.x;
    for (int i = tid; i < 512;  i += 256) w1_s[i] = w1[i];
    for (int i = tid; i < 1024; i += 256) w2_s[i] = w2[i];
    if (tid < 32) {
        p_s[tid]       = b1[tid];
        p_s[32  + tid] = g1[tid];
        p_s[64  + tid] = be1[tid];
        p_s[96  + tid] = b2[tid];
        p_s[128 + tid] = g2[tid];
        p_s[160 + tid] = be2[tid];
    }
    __syncthreads();

    int w = tid >> 5;
    int m = tid & 31;
    int e = blockIdx.x * 8 + w;   // E divisible by 8*1250 exactly

    float xv = (m < EDGE_F) ? inv[e * EDGE_F + m] : 0.0f;

    float y = p_s[m];  // b1[m]
    #pragma unroll
    for (int in = 0; in < EDGE_F; in++)
        y = fmaf(__shfl_sync(0xffffffffu, xv, in), w1_s[m * 16 + in], y);
    y = ln_relu_32(y, p_s[32 + m], p_s[64 + m]);

    float y2 = p_s[96 + m];  // b2[m]
    #pragma unroll
    for (int k = 0; k < 32; k++)
        y2 = fmaf(__shfl_sync(0xffffffffu, y, k), w2_s[m * 32 + k], y2);
    y2 = ln_relu_32(y2, p_s[128 + m], p_s[160 + m]);

    g_h[e * 32 + m] = y2;
}

// ---------------------------------------------------------------------------
// Kernel 2: fused  tmp = feat@basis ; rw = h@w3T ; out = rw@tmp
// Block = 8 edges, 256 threads. Loop f=0..43.
//   W_s[m][p]  : w3 slice for this f, p = ci*16+co (transposed for reuse)
//   T slice    : T[e][ci][o] = sum_in feat[e,ci,in]*basis[e,in,f*16+o]
//   R slice    : R[e][p]     = sum_m  h[e,m]*W_s[m][p]
//   out[e,co,o]+= sum_ci R[e][ci*16+co]*T[e][ci][o]   (register accumulators)
// ---------------------------------------------------------------------------
__global__ void __launch_bounds__(256) conv_main_kernel(
    const float* __restrict__ features,  // [E,16,16]
    const float* __restrict__ basis,     // [E,16,44,16]
    const float* __restrict__ w3,        // [11264,32]
    float*       __restrict__ out)       // [E,16,16]
{
    extern __shared__ float sm[];
    float* W_s = sm;              // 32*256 = 8192
    float* Ts  = W_s + 8192;      // 8*256  = 2048
    float* Rs  = Ts + 2048;       // 8*260  = 2080 (padded rows: 260 floats, 16B-aligned)
    float* h_s = Rs + 2080;       // 8*33   = 264  (padded rows)

    const int t  = threadIdx.x;
    const int e0 = blockIdx.x * EB;

    // load h for the 8 edges (padded layout)
    {
        int e = t >> 5, m = t & 31;
        h_s[e * 33 + m] = g_h[(e0 + e) * 32 + m];
    }

    // --- role ids ---
    const int w  = t >> 5;            // warp == edge for steps 2 & 4
    const int l  = t & 31;
    // step2: lane -> (ci, o-octet)
    const int ci = l & 15;
    const int o0 = (l >> 4) << 3;
    // step3: thread -> (e3, p-octet)
    const int e3 = t & 7;
    const int p0 = (t >> 3) << 3;
    // step4: lane -> (co, o-half)
    const int co4 = l >> 1;
    const int oo  = (l & 1) << 3;

    // features row held in registers for the whole f-loop
    float Freg[16];
    {
        const float* fptr = features + ((e0 + w) * 16 + ci) * 16;
        #pragma unroll
        for (int in = 0; in < 16; in++) Freg[in] = fptr[in];
    }

    float acc[8];
    #pragma unroll
    for (int i = 0; i < 8; i++) acc[i] = 0.0f;

    // w3 row for this thread's p in the W-load step: p = t
    const int  r_base = (t & 15) * 704 + (t >> 4) * 44;  // + f
    const float* bptr_base = basis + (e0 + w) * (16 * 704) + o0;  // + f*16 + in*704

    __syncthreads();  // h_s ready

    for (int f = 0; f < FREQ; f++) {
        if (f > 0) __syncthreads();  // prev step4 done (Ts/Rs/W_s reusable)

        // ---- load w3 slice (transposed): W_s[m][p] = w3[r(p)][m], p = t ----
        {
            const float4* row = reinterpret_cast<const float4*>(w3 + (size_t)(r_base + f) * 32);
            #pragma unroll
            for (int k = 0; k < 8; k++) {
                float4 v = row[k];
                W_s[(4 * k + 0) * 256 + t] = v.x;
                W_s[(4 * k + 1) * 256 + t] = v.y;
                W_s[(4 * k + 2) * 256 + t] = v.z;
                W_s[(4 * k + 3) * 256 + t] = v.w;
            }
        }

        // ---- step2: T[e][ci][o0..o0+7] from global basis + Freg ----
        {
            float t8[8];
            #pragma unroll
            for (int i = 0; i < 8; i++) t8[i] = 0.0f;
            const float* bp = bptr_base + f * 16;
            #pragma unroll
            for (int in = 0; in < 16; in++) {
                float fv = Freg[in];
                float4 ba = *reinterpret_cast<const float4*>(bp + in * 704);
                float4 bb = *reinterpret_cast<const float4*>(bp + in * 704 + 4);
                t8[0] = fmaf(fv, ba.x, t8[0]);
                t8[1] = fmaf(fv, ba.y, t8[1]);
                t8[2] = fmaf(fv, ba.z, t8[2]);
                t8[3] = fmaf(fv, ba.w, t8[3]);
                t8[4] = fmaf(fv, bb.x, t8[4]);
                t8[5] = fmaf(fv, bb.y, t8[5]);
                t8[6] = fmaf(fv, bb.z, t8[6]);
                t8[7] = fmaf(fv, bb.w, t8[7]);
            }
            float* tp = Ts + w * 256 + ci * 16 + o0;
            *reinterpret_cast<float4*>(tp)     = make_float4(t8[0], t8[1], t8[2], t8[3]);
            *reinterpret_cast<float4*>(tp + 4) = make_float4(t8[4], t8[5], t8[6], t8[7]);
        }

        __syncthreads();  // W_s + Ts complete

        // ---- step3: R[e3][p0..p0+7] = sum_m h[e3][m] * W_s[m][p] ----
        {
            float r8[8];
            #pragma unroll
            for (int i = 0; i < 8; i++) r8[i] = 0.0f;
            const float* hrow = h_s + e3 * 33;
            #pragma unroll
            for (int m = 0; m < 32; m++) {
                float hv = hrow[m];
                float4 wa = *reinterpret_cast<const float4*>(&W_s[m * 256 + p0]);
                float4 wb = *reinterpret_cast<const float4*>(&W_s[m * 256 + p0 + 4]);
                r8[0] = fmaf(hv, wa.x, r8[0]);
                r8[1] = fmaf(hv, wa.y, r8[1]);
                r8[2] = fmaf(hv, wa.z, r8[2]);
                r8[3] = fmaf(hv, wa.w, r8[3]);
                r8[4] = fmaf(hv, wb.x, r8[4]);
                r8[5] = fmaf(hv, wb.y, r8[5]);
                r8[6] = fmaf(hv, wb.z, r8[6]);
                r8[7] = fmaf(hv, wb.w, r8[7]);
            }
            float* rp = Rs + e3 * 260 + p0;
            *reinterpret_cast<float4*>(rp)     = make_float4(r8[0], r8[1], r8[2], r8[3]);
            *reinterpret_cast<float4*>(rp + 4) = make_float4(r8[4], r8[5], r8[6], r8[7]);
        }

        __syncthreads();  // Rs complete

        // ---- step4: acc[o] += sum_ci R[e][ci*16+co] * T[e][ci][o] ----
        {
            const float* Re = Rs + w * 260;
            const float* Te = Ts + w * 256;
            #pragma unroll
            for (int c = 0; c < 16; c++) {
                float rv = Re[c * 16 + co4];
                float4 ta = *reinterpret_cast<const float4*>(Te + c * 16 + oo);
                float4 tb = *reinterpret_cast<const float4*>(Te + c * 16 + oo + 4);
                acc[0] = fmaf(rv, ta.x, acc[0]);
                acc[1] = fmaf(rv, ta.y, acc[1]);
                acc[2] = fmaf(rv, ta.z, acc[2]);
                acc[3] = fmaf(rv, ta.w, acc[3]);
                acc[4] = fmaf(rv, tb.x, acc[4]);
                acc[5] = fmaf(rv, tb.y, acc[5]);
                acc[6] = fmaf(rv, tb.z, acc[6]);
                acc[7] = fmaf(rv, tb.w, acc[7]);
            }
        }
    }

    // epilogue: out[e][co][oo..oo+7]
    float* op = out + ((size_t)(e0 + w) * 16 + co4) * 16 + oo;
    *reinterpret_cast<float4*>(op)     = make_float4(acc[0], acc[1], acc[2], acc[3]);
    *reinterpret_cast<float4*>(op + 4) = make_float4(acc[4], acc[5], acc[6], acc[7]);
}

// ---------------------------------------------------------------------------
extern "C" void kernel_launch(void* const* d_in, const int* in_sizes, int n_in,
                              void* d_out, int out_size)
{
    const float* features = (const float*)d_in[0];
    const float* inv      = (const float*)d_in[1];
    const float* basis    = (const float*)d_in[2];
    const float* w1  = (const float*)d_in[3];
    const float* b1  = (const float*)d_in[4];
    const float* g1  = (const float*)d_in[5];
    const float* be1 = (const float*)d_in[6];
    const float* w2  = (const float*)d_in[7];
    const float* b2  = (const float*)d_in[8];
    const float* g2  = (const float*)d_in[9];
    const float* be2 = (const float*)d_in[10];
    const float* w3  = (const float*)d_in[11];
    float* out = (float*)d_out;

    const int smem_bytes = (8192 + 2048 + 2080 + 264) * 4;  // 50336
    cudaFuncSetAttribute(conv_main_kernel,
                         cudaFuncAttributeMaxDynamicSharedMemorySize, smem_bytes);

    mlp_kernel<<<NBLK, 256>>>(inv, w1, b1, g1, be1, w2, b2, g2, be2);
    conv_main_kernel<<<NBLK, 256, smem_bytes>>>(features, basis, w3, out);
}

// round 2
// speedup vs baseline: 1.3098x; 1.3098x over previous
#include <cuda_runtime.h>
#include <cuda_bf16.h>

typedef unsigned long long u64;

#define E_TOT   10000
#define FREQ    44
#define EB      16                // edges per block (conv kernel)
#define NBLK    (E_TOT / EB)      // 625
#define LN_EPS  1e-5f

// scratch for MLP output h[E,32]
__device__ float g_h[E_TOT * 32];

// ---------------------------------------------------------------------------
// packed f32x2 helpers (sm_100+)
// ---------------------------------------------------------------------------
__device__ __forceinline__ u64 f2fma(u64 a, u64 b, u64 c) {
    u64 d;
    asm("fma.rn.f32x2 %0, %1, %2, %3;" : "=l"(d) : "l"(a), "l"(b), "l"(c));
    return d;
}
__device__ __forceinline__ u64 dup2(float x) {
    u64 d;
    asm("mov.b64 %0, {%1, %1};" : "=l"(d) : "f"(x));
    return d;
}

// ---------------------------------------------------------------------------
// Kernel 1: RadialProfile MLP front (Linear->LN->ReLU->Linear->LN->ReLU)
// warp per edge, lane = hidden unit m (0..31)
// ---------------------------------------------------------------------------
__device__ __forceinline__ float ln_relu_32(float y, float gamma, float beta) {
    float s = y, q = y * y;
    #pragma unroll
    for (int d = 16; d > 0; d >>= 1) {
        s += __shfl_xor_sync(0xffffffffu, s, d);
        q += __shfl_xor_sync(0xffffffffu, q, d);
    }
    float mean = s * (1.0f / 32.0f);
    float var  = q * (1.0f / 32.0f) - mean * mean;
    float r = rsqrtf(var + LN_EPS);
    float v = (y - mean) * r * gamma + beta;
    return fmaxf(v, 0.0f);
}

__global__ void __launch_bounds__(256) mlp_kernel(
    const float* __restrict__ inv,
    const float* __restrict__ w1, const float* __restrict__ b1,
    const float* __restrict__ g1, const float* __restrict__ be1,
    const float* __restrict__ w2, const float* __restrict__ b2,
    const float* __restrict__ g2, const float* __restrict__ be2)
{
    __shared__ float w1_s[32 * 16];
    __shared__ float w2_s[32 * 32];
    __shared__ float p_s[6 * 32];

    int tid = threadIdx.x;
    for (int i = tid; i < 512;  i += 256) w1_s[i] = w1[i];
    for (int i = tid; i < 1024; i += 256) w2_s[i] = w2[i];
    if (tid < 32) {
        p_s[tid]       = b1[tid];
        p_s[32  + tid] = g1[tid];
        p_s[64  + tid] = be1[tid];
        p_s[96  + tid] = b2[tid];
        p_s[128 + tid] = g2[tid];
        p_s[160 + tid] = be2[tid];
    }
    __syncthreads();

    int w = tid >> 5;
    int m = tid & 31;
    int e = blockIdx.x * 8 + w;

    float xv = (m < 16) ? inv[e * 16 + m] : 0.0f;

    float y = p_s[m];
    #pragma unroll
    for (int in = 0; in < 16; in++)
        y = fmaf(__shfl_sync(0xffffffffu, xv, in), w1_s[m * 16 + in], y);
    y = ln_relu_32(y, p_s[32 + m], p_s[64 + m]);

    float y2 = p_s[96 + m];
    #pragma unroll
    for (int k = 0; k < 32; k++)
        y2 = fmaf(__shfl_sync(0xffffffffu, y, k), w2_s[m * 32 + k], y2);
    y2 = ln_relu_32(y2, p_s[128 + m], p_s[160 + m]);

    g_h[e * 32 + m] = y2;
}

// ---------------------------------------------------------------------------
// Kernel 2: fused  tmp = feat@basis ; rw = h@w3T ; out = rw@tmp
// Block = 16 edges, 256 threads, loop f = 0..43.
//
// p index = ci*16 + co (w3 row = co*704 + ci*44 + f).
// W_s[m][.] uses a split-octet layout: octet q's first 4 words at [q*4],
//   second 4 at [128 + q*4]  -> lane reads are stride-16B, conflict-free.
// Ts[e][ci*16 + chunk-swizzled o] : chunk k stored at (k ^ (ci&3))*4.
// Rs[ms][e][.] in the same split-octet layout, ms = m-half partial sums.
// hd[m][e] holds (h,h) duplicated pairs so step3 gets its scalar operand
//   pre-packed from a broadcast LDS.64/128.
// ---------------------------------------------------------------------------
__global__ void __launch_bounds__(256, 2) conv_main_kernel(
    const float* __restrict__ features,  // [E,16,16]
    const float* __restrict__ basis,     // [E,16,44,16]
    const float* __restrict__ w3,        // [11264,32]
    float*       __restrict__ out)       // [E,16,16]
{
    extern __shared__ float sm[];
    float* W_s = sm;                 // 32*256          = 8192 floats
    float* Ts  = sm + 8192;          // 16*256          = 4096
    float* Rs  = sm + 12288;         // 2*16*264        = 8448
    float* hd  = sm + 20736;         // 32*16*2 (dup)   = 1024
                                     // total 21760 floats = 87040 B

    const int t  = threadIdx.x;
    const int e0 = blockIdx.x * EB;

    // ---- stage hd: duplicated-pair copies of h for the 16 edges ----
    {
        int e = t & 15, m = t >> 4;
        float v0 = g_h[(e0 + e) * 32 + m];
        hd[(m * 16 + e) * 2]     = v0;
        hd[(m * 16 + e) * 2 + 1] = v0;
        float v1 = g_h[(e0 + e) * 32 + m + 16];
        hd[((m + 16) * 16 + e) * 2]     = v1;
        hd[((m + 16) * 16 + e) * 2 + 1] = v1;
    }

    // ---- role ids ----
    const int lane = t & 31;
    const int ms   = (t >> 5) & 1;     // m-half for step3
    const int et   = t >> 6;           // e-tile (4 edges) for step3
    const int e2   = t >> 4;           // edge for step2 / step4
    const int ci   = t & 15;           // step2
    const int co   = t & 15;           // step4
    // W staging: thread owns w3 row for p = t, scattered into split layout
    const int colW  = ((t >> 3) << 2) + (((t >> 2) & 1) << 7) + (t & 3);
    const int rowW3 = (t & 15) * 704 + (t >> 4) * 44;
    // step4: physical column of p = ci*16+co in split layout = Rcol0 + 8*ci
    const int Rcol0 = (((co >> 2) & 1) << 7) + ((co >> 3) << 2) + (co & 3);

    // features row for (e2, ci), registers for the whole f loop
    float Freg[16];
    {
        const float* fp = features + ((e0 + e2) * 16 + ci) * 16;
        #pragma unroll
        for (int i = 0; i < 16; i++) Freg[i] = fp[i];
    }

    u64 accO[8];
    #pragma unroll
    for (int i = 0; i < 8; i++) accO[i] = 0ull;

    const float* basE = basis + (e0 + e2) * (16 * 704);

    for (int f = 0; f < FREQ; f++) {
        if (f) __syncthreads();   // prev step4 done reading Ts; Rs/W_s free

        // ---- stage W slice (split-octet layout) ----
        {
            const float4* wr = reinterpret_cast<const float4*>(w3 + (rowW3 + f) * 32);
            #pragma unroll
            for (int k = 0; k < 8; k++) {
                float4 v = wr[k];
                W_s[(4 * k + 0) * 256 + colW] = v.x;
                W_s[(4 * k + 1) * 256 + colW] = v.y;
                W_s[(4 * k + 2) * 256 + colW] = v.z;
                W_s[(4 * k + 3) * 256 + colW] = v.w;
            }
        }

        // ---- step2: T[e2][ci][0..15] from basis (broadcast LDG) ----
        {
            u64 t8[8];
            #pragma unroll
            for (int i = 0; i < 8; i++) t8[i] = 0ull;
            const float* bp0 = basE + f * 16;
            #pragma unroll
            for (int in = 0; in < 16; in++) {
                const ulonglong2* bp = reinterpret_cast<const ulonglong2*>(bp0 + in * 704);
                u64 fd = dup2(Freg[in]);
                ulonglong2 b0 = bp[0], b1 = bp[1], b2 = bp[2], b3 = bp[3];
                t8[0] = f2fma(fd, b0.x, t8[0]); t8[1] = f2fma(fd, b0.y, t8[1]);
                t8[2] = f2fma(fd, b1.x, t8[2]); t8[3] = f2fma(fd, b1.y, t8[3]);
                t8[4] = f2fma(fd, b2.x, t8[4]); t8[5] = f2fma(fd, b2.y, t8[5]);
                t8[6] = f2fma(fd, b3.x, t8[6]); t8[7] = f2fma(fd, b3.y, t8[7]);
            }
            float* tb = Ts + e2 * 256 + ci * 16;
            const int sw = ci & 3;
            *reinterpret_cast<ulonglong2*>(tb + ((0 ^ sw) << 2)) = make_ulonglong2(t8[0], t8[1]);
            *reinterpret_cast<ulonglong2*>(tb + ((1 ^ sw) << 2)) = make_ulonglong2(t8[2], t8[3]);
            *reinterpret_cast<ulonglong2*>(tb + ((2 ^ sw) << 2)) = make_ulonglong2(t8[4], t8[5]);
            *reinterpret_cast<ulonglong2*>(tb + ((3 ^ sw) << 2)) = make_ulonglong2(t8[6], t8[7]);
        }

        __syncthreads();  // W_s + Ts complete

        // ---- step3: R[4e][8p] partial over 16 m, register tile ----
        {
            u64 acc[4][4];
            #pragma unroll
            for (int e = 0; e < 4; e++)
                #pragma unroll
                for (int p = 0; p < 4; p++) acc[e][p] = 0ull;

            const float* hb = hd + ((ms << 4) * 16 + (et << 2)) * 2;
            const float* wb = W_s + (ms << 4) * 256 + (lane << 2);
            #pragma unroll
            for (int m = 0; m < 16; m++) {
                ulonglong2 hA = *reinterpret_cast<const ulonglong2*>(hb + (m << 5));
                ulonglong2 hB = *reinterpret_cast<const ulonglong2*>(hb + (m << 5) + 4);
                ulonglong2 wA = *reinterpret_cast<const ulonglong2*>(wb + (m << 8));
                ulonglong2 wB = *reinterpret_cast<const ulonglong2*>(wb + (m << 8) + 128);
                acc[0][0] = f2fma(hA.x, wA.x, acc[0][0]);
                acc[0][1] = f2fma(hA.x, wA.y, acc[0][1]);
                acc[0][2] = f2fma(hA.x, wB.x, acc[0][2]);
                acc[0][3] = f2fma(hA.x, wB.y, acc[0][3]);
                acc[1][0] = f2fma(hA.y, wA.x, acc[1][0]);
                acc[1][1] = f2fma(hA.y, wA.y, acc[1][1]);
                acc[1][2] = f2fma(hA.y, wB.x, acc[1][2]);
                acc[1][3] = f2fma(hA.y, wB.y, acc[1][3]);
                acc[2][0] = f2fma(hB.x, wA.x, acc[2][0]);
                acc[2][1] = f2fma(hB.x, wA.y, acc[2][1]);
                acc[2][2] = f2fma(hB.x, wB.x, acc[2][2]);
                acc[2][3] = f2fma(hB.x, wB.y, acc[2][3]);
                acc[3][0] = f2fma(hB.y, wA.x, acc[3][0]);
                acc[3][1] = f2fma(hB.y, wA.y, acc[3][1]);
                acc[3][2] = f2fma(hB.y, wB.x, acc[3][2]);
                acc[3][3] = f2fma(hB.y, wB.y, acc[3][3]);
            }
            float* rb = Rs + ms * (16 * 264) + (lane << 2);
            #pragma unroll
            for (int e = 0; e < 4; e++) {
                float* rr = rb + ((et << 2) + e) * 264;
                *reinterpret_cast<ulonglong2*>(rr)       = make_ulonglong2(acc[e][0], acc[e][1]);
                *reinterpret_cast<ulonglong2*>(rr + 128) = make_ulonglong2(acc[e][2], acc[e][3]);
            }
        }

        __syncthreads();  // Rs complete

        // ---- step4: accO[o] += (R0+R1)[e][ci*16+co] * T[e][ci][o] ----
        {
            const float* r0 = Rs + e2 * 264 + Rcol0;
            const float* r1 = r0 + 16 * 264;
            const float* tb = Ts + e2 * 256;
            #pragma unroll
            for (int c = 0; c < 16; c++) {
                float rv = r0[c * 8] + r1[c * 8];
                u64 rd = dup2(rv);
                const float* tc = tb + c * 16;
                const int sw = c & 3;
                ulonglong2 c0 = *reinterpret_cast<const ulonglong2*>(tc + ((0 ^ sw) << 2));
                ulonglong2 c1 = *reinterpret_cast<const ulonglong2*>(tc + ((1 ^ sw) << 2));
                ulonglong2 c2 = *reinterpret_cast<const ulonglong2*>(tc + ((2 ^ sw) << 2));
                ulonglong2 c3 = *reinterpret_cast<const ulonglong2*>(tc + ((3 ^ sw) << 2));
                accO[0] = f2fma(rd, c0.x, accO[0]); accO[1] = f2fma(rd, c0.y, accO[1]);
                accO[2] = f2fma(rd, c1.x, accO[2]); accO[3] = f2fma(rd, c1.y, accO[3]);
                accO[4] = f2fma(rd, c2.x, accO[4]); accO[5] = f2fma(rd, c2.y, accO[5]);
                accO[6] = f2fma(rd, c3.x, accO[6]); accO[7] = f2fma(rd, c3.y, accO[7]);
            }
        }
    }

    // ---- epilogue: out[e][co][0..15] ----
    float* op = out + ((size_t)(e0 + e2) * 16 + co) * 16;
    *reinterpret_cast<ulonglong2*>(op)      = make_ulonglong2(accO[0], accO[1]);
    *reinterpret_cast<ulonglong2*>(op + 4)  = make_ulonglong2(accO[2], accO[3]);
    *reinterpret_cast<ulonglong2*>(op + 8)  = make_ulonglong2(accO[4], accO[5]);
    *reinterpret_cast<ulonglong2*>(op + 12) = make_ulonglong2(accO[6], accO[7]);
}

// ---------------------------------------------------------------------------
extern "C" void kernel_launch(void* const* d_in, const int* in_sizes, int n_in,
                              void* d_out, int out_size)
{
    const float* features = (const float*)d_in[0];
    const float* inv      = (const float*)d_in[1];
    const float* basis    = (const float*)d_in[2];
    const float* w1  = (const float*)d_in[3];
    const float* b1  = (const float*)d_in[4];
    const float* g1  = (const float*)d_in[5];
    const float* be1 = (const float*)d_in[6];
    const float* w2  = (const float*)d_in[7];
    const float* b2  = (const float*)d_in[8];
    const float* g2  = (const float*)d_in[9];
    const float* be2 = (const float*)d_in[10];
    const float* w3  = (const float*)d_in[11];
    float* out = (float*)d_out;

    const int smem_bytes = 21760 * 4;  // 87040
    cudaFuncSetAttribute(conv_main_kernel,
                         cudaFuncAttributeMaxDynamicSharedMemorySize, smem_bytes);

    mlp_kernel<<<E_TOT / 8, 256>>>(inv, w1, b1, g1, be1, w2, b2, g2, be2);
    conv_main_kernel<<<NBLK, 256, smem_bytes>>>(features, basis, w3, out);
}

// round 4
// speedup vs baseline: 1.4499x; 1.1070x over previous
#include <cuda_runtime.h>
#include <cuda_bf16.h>

typedef unsigned long long u64;

#define E_TOT   10000
#define FREQ    44
#define EB      32
#define NBLK    ((E_TOT + EB - 1) / EB)   // 313
#define LN_EPS  1e-5f

// scratch
__device__ float g_h[E_TOT * 32];
__device__ float g_w3t[FREQ * 32 * 256];   // [f][m][p], p = ci*16+co

// ---------------------------------------------------------------------------
__device__ __forceinline__ u64 f2fma(u64 a, u64 b, u64 c) {
    u64 d;
    asm("fma.rn.f32x2 %0, %1, %2, %3;" : "=l"(d) : "l"(a), "l"(b), "l"(c));
    return d;
}
__device__ __forceinline__ u64 dup2(float x) {
    u64 d;
    asm("mov.b64 %0, {%1, %1};" : "=l"(d) : "f"(x));
    return d;
}
__device__ __forceinline__ ulonglong2 ldg2g(const float* p, bool v) {
    if (v) return *reinterpret_cast<const ulonglong2*>(p);
    return make_ulonglong2(0ull, 0ull);
}

// ---------------------------------------------------------------------------
// Kernel 0: transpose w3 -> g_w3t[f][m][p],  p = ci*16+co, w3 row = co*704+ci*44+f
// ---------------------------------------------------------------------------
__global__ void w3t_kernel(const float* __restrict__ w3) {
    int idx = blockIdx.x * 256 + threadIdx.x;
    if (idx < FREQ * 32 * 256) {
        int p = idx & 255;
        int m = (idx >> 8) & 31;
        int f = idx >> 13;
        int row = (p & 15) * 704 + (p >> 4) * 44 + f;
        g_w3t[idx] = w3[row * 32 + m];
    }
}

// ---------------------------------------------------------------------------
// Kernel 1: RadialProfile MLP
// ---------------------------------------------------------------------------
__device__ __forceinline__ float ln_relu_32(float y, float gamma, float beta) {
    float s = y, q = y * y;
    #pragma unroll
    for (int d = 16; d > 0; d >>= 1) {
        s += __shfl_xor_sync(0xffffffffu, s, d);
        q += __shfl_xor_sync(0xffffffffu, q, d);
    }
    float mean = s * (1.0f / 32.0f);
    float var  = q * (1.0f / 32.0f) - mean * mean;
    float r = rsqrtf(var + LN_EPS);
    float v = (y - mean) * r * gamma + beta;
    return fmaxf(v, 0.0f);
}

__global__ void __launch_bounds__(256) mlp_kernel(
    const float* __restrict__ inv,
    const float* __restrict__ w1, const float* __restrict__ b1,
    const float* __restrict__ g1, const float* __restrict__ be1,
    const float* __restrict__ w2, const float* __restrict__ b2,
    const float* __restrict__ g2, const float* __restrict__ be2)
{
    __shared__ float w1_s[32 * 16];
    __shared__ float w2_s[32 * 32];
    __shared__ float p_s[6 * 32];

    int tid = threadIdx.x;
    for (int i = tid; i < 512;  i += 256) w1_s[i] = w1[i];
    for (int i = tid; i < 1024; i += 256) w2_s[i] = w2[i];
    if (tid < 32) {
        p_s[tid]       = b1[tid];
        p_s[32  + tid] = g1[tid];
        p_s[64  + tid] = be1[tid];
        p_s[96  + tid] = b2[tid];
        p_s[128 + tid] = g2[tid];
        p_s[160 + tid] = be2[tid];
    }
    __syncthreads();

    int w = tid >> 5;
    int m = tid & 31;
    int e = blockIdx.x * 8 + w;

    float xv = (m < 16) ? inv[e * 16 + m] : 0.0f;

    float y = p_s[m];
    #pragma unroll
    for (int in = 0; in < 16; in++)
        y = fmaf(__shfl_sync(0xffffffffu, xv, in), w1_s[m * 16 + in], y);
    y = ln_relu_32(y, p_s[32 + m], p_s[64 + m]);

    float y2 = p_s[96 + m];
    #pragma unroll
    for (int k = 0; k < 32; k++)
        y2 = fmaf(__shfl_sync(0xffffffffu, y, k), w2_s[m * 32 + k], y2);
    y2 = ln_relu_32(y2, p_s[128 + m], p_s[160 + m]);

    g_h[e * 32 + m] = y2;
}

// ---------------------------------------------------------------------------
// Kernel 2: fused conv, EB=32 edges / block, 256 threads.
//
// smem:
//  Ts[e][256]  : T slice; o-chunk k stored at kk = k ^ ((ci>>1)&3) ^ ((e>>4)&1)<<1
//  Rs[e][264]  : R slice; column p stored at p ^ (e & 16)
//  hs[m][32]   : h transposed (pair loads along edges)
//  fs[e][ci][in] : features copy
// ---------------------------------------------------------------------------
__global__ void __launch_bounds__(256, 2) conv_main_kernel(
    const float* __restrict__ features,  // [E,16,16]
    const float* __restrict__ basis,     // [E,16,44,16]
    float*       __restrict__ out)       // [E,16,16]
{
    extern __shared__ float sm[];
    float* Ts = sm;                  // 32*256 = 8192
    float* Rs = sm + 8192;           // 32*264 = 8448
    float* hs = sm + 16640;          // 32*32  = 1024
    float* fs = sm + 17664;          // 32*256 = 8192  -> total 25856 floats

    const int t  = threadIdx.x;
    const int e0 = blockIdx.x * EB;

    // stage hs[m][e]
    #pragma unroll
    for (int i = 0; i < 4; i++) {
        int idx = t + i * 256;
        int m = idx >> 5, e = idx & 31;
        hs[m * 32 + e] = (e0 + e < E_TOT) ? g_h[(e0 + e) * 32 + m] : 0.0f;
    }
    // stage fs (32 edges * 256 floats = 8192 -> 32 iterations of 256 threads)
    #pragma unroll
    for (int i = 0; i < 32; i++) {
        int idx = t + i * 256;
        int e = idx >> 8;
        fs[idx] = (e0 + e < E_TOT) ? features[(size_t)(e0 + e) * 256 + (idx & 255)] : 0.0f;
    }

    // roles
    const int e2  = t >> 3;              // step2 edge
    const int ci0 = t & 7;               // step2 ci (and ci+8)
    const int et  = t >> 7;              // step3 e-tile (16 edges)
    const int p0  = (t & 127) * 2;       // step3 p pair
    const int w   = t >> 5;              // warp
    const int l   = t & 31;
    const int co  = l & 15;              // step4
    const int eh  = (l >> 4) << 4;       // step4 half offset (0 or 16)

    const bool v2 = (e0 + e2) < E_TOT;
    const float* basE = basis + (size_t)(e0 + e2) * 11264;

    u64 accO[2][8];
    #pragma unroll
    for (int r = 0; r < 2; r++)
        #pragma unroll
        for (int i = 0; i < 8; i++) accO[r][i] = 0ull;

    const int sw2  = (ci0 >> 1) & 3;
    const int swe2 = ((e2 >> 4) & 1) << 1;

    __syncthreads();

    for (int f = 0; f < FREQ; f++) {
        if (f) __syncthreads();   // prev step4 done with Ts/Rs

        // ================= step2: T rows (e2, ci0) and (e2, ci0+8) ==========
        {
            float fA[16], fB[16];
            {
                const float4* pa = reinterpret_cast<const float4*>(fs + (e2 * 16 + ci0) * 16);
                const float4* pb = reinterpret_cast<const float4*>(fs + (e2 * 16 + ci0 + 8) * 16);
                #pragma unroll
                for (int k = 0; k < 4; k++) {
                    float4 a = pa[k], b = pb[k];
                    fA[4*k] = a.x; fA[4*k+1] = a.y; fA[4*k+2] = a.z; fA[4*k+3] = a.w;
                    fB[4*k] = b.x; fB[4*k+1] = b.y; fB[4*k+2] = b.z; fB[4*k+3] = b.w;
                }
            }
            u64 tA[8], tB[8];
            #pragma unroll
            for (int i = 0; i < 8; i++) { tA[i] = 0ull; tB[i] = 0ull; }

            const float* bp = basE + f * 16;
            #pragma unroll 4
            for (int in = 0; in < 16; in++) {
                const float* q = bp + in * 704;
                ulonglong2 x0 = ldg2g(q,      v2);
                ulonglong2 x1 = ldg2g(q + 4,  v2);
                ulonglong2 x2 = ldg2g(q + 8,  v2);
                ulonglong2 x3 = ldg2g(q + 12, v2);
                u64 da = dup2(fA[in]);
                u64 db = dup2(fB[in]);
                tA[0] = f2fma(da, x0.x, tA[0]); tA[1] = f2fma(da, x0.y, tA[1]);
                tA[2] = f2fma(da, x1.x, tA[2]); tA[3] = f2fma(da, x1.y, tA[3]);
                tA[4] = f2fma(da, x2.x, tA[4]); tA[5] = f2fma(da, x2.y, tA[5]);
                tA[6] = f2fma(da, x3.x, tA[6]); tA[7] = f2fma(da, x3.y, tA[7]);
                tB[0] = f2fma(db, x0.x, tB[0]); tB[1] = f2fma(db, x0.y, tB[1]);
                tB[2] = f2fma(db, x1.x, tB[2]); tB[3] = f2fma(db, x1.y, tB[3]);
                tB[4] = f2fma(db, x2.x, tB[4]); tB[5] = f2fma(db, x2.y, tB[5]);
                tB[6] = f2fma(db, x3.x, tB[6]); tB[7] = f2fma(db, x3.y, tB[7]);
            }
            float* ta = Ts + e2 * 256 + ci0 * 16;
            float* tb = ta + 128;          // ci0 + 8
            #pragma unroll
            for (int k = 0; k < 4; k++) {
                int kk = k ^ sw2 ^ swe2;
                *reinterpret_cast<ulonglong2*>(ta + (kk << 2)) = make_ulonglong2(tA[2*k], tA[2*k+1]);
                *reinterpret_cast<ulonglong2*>(tb + (kk << 2)) = make_ulonglong2(tB[2*k], tB[2*k+1]);
            }
        }

        // ================= step3: R[16e][2p] from g_w3t ======================
        {
            u64 acc[8][2];
            #pragma unroll
            for (int i = 0; i < 8; i++) { acc[i][0] = 0ull; acc[i][1] = 0ull; }

            const float* wp = g_w3t + (size_t)f * 8192 + p0;
            const float* hp = hs + (et << 4);
            #pragma unroll 8
            for (int m = 0; m < 32; m++) {
                float2 wv = *reinterpret_cast<const float2*>(wp + m * 256);
                u64 w0 = dup2(wv.x);
                u64 w1 = dup2(wv.y);
                const u64* hq = reinterpret_cast<const u64*>(hp + m * 32);
                #pragma unroll
                for (int i = 0; i < 8; i++) {
                    u64 hv = hq[i];
                    acc[i][0] = f2fma(hv, w0, acc[i][0]);
                    acc[i][1] = f2fma(hv, w1, acc[i][1]);
                }
            }
            const int px = p0 ^ (et << 4);
            #pragma unroll
            for (int i = 0; i < 8; i++) {
                float2 a0 = *reinterpret_cast<float2*>(&acc[i][0]);
                float2 a1 = *reinterpret_cast<float2*>(&acc[i][1]);
                float* r0 = Rs + ((et << 4) + 2 * i) * 264 + px;
                float* r1 = r0 + 264;
                *reinterpret_cast<float2*>(r0) = make_float2(a0.x, a1.x);
                *reinterpret_cast<float2*>(r1) = make_float2(a0.y, a1.y);
            }
        }

        __syncthreads();   // Ts + Rs ready

        // ================= step4: out accum =================================
        #pragma unroll
        for (int r = 0; r < 2; r++) {
            const int e  = w + 8 * r + eh;
            const int ex = e & 16;
            const float* Re = Rs + e * 264;
            const float* Te = Ts + e * 256;
            const int swe = ((e >> 4) & 1) << 1;
            #pragma unroll 4
            for (int c = 0; c < 16; c++) {
                float rv = Re[(c * 16 + co) ^ ex];
                u64 rd = dup2(rv);
                const float* tc = Te + c * 16;
                const int sws = ((c >> 1) & 3) ^ swe;
                ulonglong2 x0 = *reinterpret_cast<const ulonglong2*>(tc + ((0 ^ sws) << 2));
                ulonglong2 x1 = *reinterpret_cast<const ulonglong2*>(tc + ((1 ^ sws) << 2));
                ulonglong2 x2 = *reinterpret_cast<const ulonglong2*>(tc + ((2 ^ sws) << 2));
                ulonglong2 x3 = *reinterpret_cast<const ulonglong2*>(tc + ((3 ^ sws) << 2));
                accO[r][0] = f2fma(rd, x0.x, accO[r][0]);
                accO[r][1] = f2fma(rd, x0.y, accO[r][1]);
                accO[r][2] = f2fma(rd, x1.x, accO[r][2]);
                accO[r][3] = f2fma(rd, x1.y, accO[r][3]);
                accO[r][4] = f2fma(rd, x2.x, accO[r][4]);
                accO[r][5] = f2fma(rd, x2.y, accO[r][5]);
                accO[r][6] = f2fma(rd, x3.x, accO[r][6]);
                accO[r][7] = f2fma(rd, x3.y, accO[r][7]);
            }
        }
    }

    // epilogue
    #pragma unroll
    for (int r = 0; r < 2; r++) {
        const int e = w + 8 * r + eh;
        if (e0 + e < E_TOT) {
            float* op = out + ((size_t)(e0 + e) * 16 + co) * 16;
            *reinterpret_cast<ulonglong2*>(op)      = make_ulonglong2(accO[r][0], accO[r][1]);
            *reinterpret_cast<ulonglong2*>(op + 4)  = make_ulonglong2(accO[r][2], accO[r][3]);
            *reinterpret_cast<ulonglong2*>(op + 8)  = make_ulonglong2(accO[r][4], accO[r][5]);
            *reinterpret_cast<ulonglong2*>(op + 12) = make_ulonglong2(accO[r][6], accO[r][7]);
        }
    }
}

// ---------------------------------------------------------------------------
extern "C" void kernel_launch(void* const* d_in, const int* in_sizes, int n_in,
                              void* d_out, int out_size)
{
    const float* features = (const float*)d_in[0];
    const float* inv      = (const float*)d_in[1];
    const float* basis    = (const float*)d_in[2];
    const float* w1  = (const float*)d_in[3];
    const float* b1  = (const float*)d_in[4];
    const float* g1  = (const float*)d_in[5];
    const float* be1 = (const float*)d_in[6];
    const float* w2  = (const float*)d_in[7];
    const float* b2  = (const float*)d_in[8];
    const float* g2  = (const float*)d_in[9];
    const float* be2 = (const float*)d_in[10];
    const float* w3  = (const float*)d_in[11];
    float* out = (float*)d_out;

    const int smem_bytes = 25856 * 4;   // 103424
    cudaFuncSetAttribute(conv_main_kernel,
                         cudaFuncAttributeMaxDynamicSharedMemorySize, smem_bytes);

    w3t_kernel<<<(FREQ * 32 * 256 + 255) / 256, 256>>>(w3);
    mlp_kernel<<<E_TOT / 8, 256>>>(inv, w1, b1, g1, be1, w2, b2, g2, be2);
    conv_main_kernel<<<NBLK, 256, smem_bytes>>>(features, basis, out);
}